// round 15
// baseline (speedup 1.0000x reference)
#include <cuda_runtime.h>

// ---------------------------------------------------------------------------
// Exact closed form via Heisenberg/Pauli propagation (validated R14,
// rel_err ~3.5e-7):
//   F_w = cos(x_w + th0_w), G_w = sin(x_w + th0_w)
//   c_w = cos(th1_w),        s_w = sin(th1_w)
//   out0 = c1c2c3 F0F1F3 + c1c2s3 G0G1G3 + s1s2c3 F0G1G3 + s1s2s3 G0F1F3
//   out1 = c0c1 F0F2F3 + s0s1 G0G2F3
//   out2 = c0c1c2 F1F3 + c0s1s2 G1G3
//   out3 = c0c1c2c3 F0F2 + s0s1c2c3 G0G2 + c0s1s2s3 G0F2
// One sample per thread (R12-measured best latency-hiding shape).
// ---------------------------------------------------------------------------
__global__ __launch_bounds__(256) void qenc_kernel(
    const float* __restrict__ weights,
    const float4* __restrict__ x4,
    float4* __restrict__ out4,
    int n)
{
    const int i = blockIdx.x * 256 + threadIdx.x;
    if (i >= n) return;

    // Uniform weight-derived constants (broadcast loads + 8 MUFU).
    const float4 w0 = __ldg((const float4*)weights);       // th0_{0..3}
    const float4 w1 = __ldg((const float4*)(weights + 4)); // th1_{0..3}
    float c0w, s0w, c1w, s1w, c2w, s2w, c3w, s3w;
    __sincosf(w1.x, &s0w, &c0w);
    __sincosf(w1.y, &s1w, &c1w);
    __sincosf(w1.z, &s2w, &c2w);
    __sincosf(w1.w, &s3w, &c3w);

    // out0 coefficients
    const float A0 = c1w * c2w * c3w;        // F0F1F3
    const float A1 = c1w * c2w * s3w;        // G0G1G3
    const float A2 = s1w * s2w * c3w;        // F0G1G3
    const float A3 = s1w * s2w * s3w;        // G0F1F3
    // out1
    const float B0 = c0w * c1w;              // F0F2F3
    const float B1 = s0w * s1w;              // G0G2F3
    // out2
    const float C0 = c0w * c1w * c2w;        // F1F3
    const float C1 = c0w * s1w * s2w;        // G1G3
    // out3
    const float D0 = C0 * c3w;               // F0F2
    const float D1 = s0w * s1w * c2w * c3w;  // G0G2
    const float D2 = c0w * s1w * s2w * s3w;  // G0F2

    const float4 xv = x4[i];
    float F0, G0, F1, G1, F2, G2, F3, G3;
    __sincosf(xv.x + w0.x, &G0, &F0);
    __sincosf(xv.y + w0.y, &G1, &F1);
    __sincosf(xv.z + w0.z, &G2, &F2);
    __sincosf(xv.w + w0.w, &G3, &F3);

    const float F0F3 = F0 * F3, G0G3 = G0 * G3;
    const float F0G3 = F0 * G3, G0F3 = G0 * F3;

    const float o0 = fmaf(A0 * F1, F0F3,
                     fmaf(A1 * G1, G0G3,
                     fmaf(A2 * G1, F0G3, A3 * F1 * G0F3)));
    const float o1 = fmaf(B0 * F2, F0F3, B1 * G2 * G0F3);
    const float o2 = fmaf(C0, F1 * F3, C1 * (G1 * G3));
    const float o3 = fmaf(D0, F0 * F2, fmaf(D1, G0 * G2, D2 * (G0 * F2)));

    out4[i] = make_float4(o0, o1, o2, o3);
}

extern "C" void kernel_launch(void* const* d_in, const int* in_sizes, int n_in,
                              void* d_out, int out_size) {
    const float* x = (const float*)d_in[0];        // [B, 4] float32
    const float* weights = (const float*)d_in[1];  // [2, 4] float32
    float* out = (float*)d_out;                    // [B, 4] float32

    const int n = in_sizes[0] / 4;

    qenc_kernel<<<(n + 255) / 256, 256>>>(
        weights, (const float4*)x, (float4*)out, n);
}

// round 16
// speedup vs baseline: 1.2657x; 1.2657x over previous
#include <cuda_runtime.h>

// ---------------------------------------------------------------------------
// Exact closed form via Heisenberg/Pauli propagation (validated R14/R15,
// rel_err ~3.5e-7):
//   F_w = cos(x_w + th0_w), G_w = sin(x_w + th0_w)
//   c_w = cos(th1_w),        s_w = sin(th1_w)
//   out0 = c1c2c3 F0F1F3 + c1c2s3 G0G1G3 + s1s2c3 F0G1G3 + s1s2s3 G0F1F3
//   out1 = c0c1 F0F2F3 + s0s1 G0G2F3
//   out2 = c0c1c2 F1F3 + c0s1s2 G1G3
//   out3 = c0c1c2c3 F0F2 + s0s1c2c3 G0G2 + c0s1s2s3 G0F2
//
// Scheduling: both sample loads issue FIRST (MLP=2); uniform coefficient
// math executes inside the DRAM-latency shadow. Regs capped at 32 via
// launch bounds to keep full occupancy.
// ---------------------------------------------------------------------------
__global__ void __launch_bounds__(256, 8) qenc_kernel(
    const float* __restrict__ weights,
    const float4* __restrict__ x4,
    float4* __restrict__ out4,
    int n, int half)
{
    const int iA = blockIdx.x * 256 + threadIdx.x;
    if (iA >= half) return;
    const int iB = iA + half;
    const bool hasB = (iB < n);

    // ---- Issue the two global loads immediately (independent, coalesced) ----
    const float4 xa = x4[iA];
    const float4 xb = x4[hasB ? iB : iA];

    // ---- Uniform coefficient math (hidden under the LDG latency) ----
    const float4 w0 = __ldg((const float4*)weights);       // th0_{0..3}
    const float4 w1 = __ldg((const float4*)(weights + 4)); // th1_{0..3}
    float c0w, s0w, c1w, s1w, c2w, s2w, c3w, s3w;
    __sincosf(w1.x, &s0w, &c0w);
    __sincosf(w1.y, &s1w, &c1w);
    __sincosf(w1.z, &s2w, &c2w);
    __sincosf(w1.w, &s3w, &c3w);

    const float A0 = c1w * c2w * c3w;        // F0F1F3
    const float A1 = c1w * c2w * s3w;        // G0G1G3
    const float A2 = s1w * s2w * c3w;        // F0G1G3
    const float A3 = s1w * s2w * s3w;        // G0F1F3
    const float B0 = c0w * c1w;              // F0F2F3
    const float B1 = s0w * s1w;              // G0G2F3
    const float C0 = c0w * c1w * c2w;        // F1F3
    const float C1 = c0w * s1w * s2w;        // G1G3
    const float D0 = C0 * c3w;               // F0F2
    const float D1 = s0w * s1w * c2w * c3w;  // G0G2
    const float D2 = c0w * s1w * s2w * s3w;  // G0F2

    // ---- Sample A ----
    {
        float F0, G0, F1, G1, F2, G2, F3, G3;
        __sincosf(xa.x + w0.x, &G0, &F0);
        __sincosf(xa.y + w0.y, &G1, &F1);
        __sincosf(xa.z + w0.z, &G2, &F2);
        __sincosf(xa.w + w0.w, &G3, &F3);

        const float F0F3 = F0 * F3, G0G3 = G0 * G3;
        const float F0G3 = F0 * G3, G0F3 = G0 * F3;

        const float o0 = fmaf(A0 * F1, F0F3,
                         fmaf(A1 * G1, G0G3,
                         fmaf(A2 * G1, F0G3, A3 * F1 * G0F3)));
        const float o1 = fmaf(B0 * F2, F0F3, B1 * G2 * G0F3);
        const float o2 = fmaf(C0, F1 * F3, C1 * (G1 * G3));
        const float o3 = fmaf(D0, F0 * F2, fmaf(D1, G0 * G2, D2 * (G0 * F2)));

        out4[iA] = make_float4(o0, o1, o2, o3);
    }

    // ---- Sample B ----
    if (hasB) {
        float F0, G0, F1, G1, F2, G2, F3, G3;
        __sincosf(xb.x + w0.x, &G0, &F0);
        __sincosf(xb.y + w0.y, &G1, &F1);
        __sincosf(xb.z + w0.z, &G2, &F2);
        __sincosf(xb.w + w0.w, &G3, &F3);

        const float F0F3 = F0 * F3, G0G3 = G0 * G3;
        const float F0G3 = F0 * G3, G0F3 = G0 * F3;

        const float o0 = fmaf(A0 * F1, F0F3,
                         fmaf(A1 * G1, G0G3,
                         fmaf(A2 * G1, F0G3, A3 * F1 * G0F3)));
        const float o1 = fmaf(B0 * F2, F0F3, B1 * G2 * G0F3);
        const float o2 = fmaf(C0, F1 * F3, C1 * (G1 * G3));
        const float o3 = fmaf(D0, F0 * F2, fmaf(D1, G0 * G2, D2 * (G0 * F2)));

        out4[iB] = make_float4(o0, o1, o2, o3);
    }
}

extern "C" void kernel_launch(void* const* d_in, const int* in_sizes, int n_in,
                              void* d_out, int out_size) {
    const float* x = (const float*)d_in[0];        // [B, 4] float32
    const float* weights = (const float*)d_in[1];  // [2, 4] float32
    float* out = (float*)d_out;                    // [B, 4] float32

    const int n = in_sizes[0] / 4;
    const int half = (n + 1) / 2;

    qenc_kernel<<<(half + 255) / 256, 256>>>(
        weights, (const float4*)x, (float4*)out, n, half);
}